// round 14
// baseline (speedup 1.0000x reference)
#include <cuda_runtime.h>
#include <cstdint>

#define N_MAX 100000
#define E_MAX 600000
#define HF 128

// ---------------- scratch (static __device__ — no allocation) ----------------
__device__ __align__(16) float d_bufA[N_MAX * HF];
__device__ __align__(16) float d_bufB[N_MAX * HF];
__device__ int   d_cnt[N_MAX];
__device__ int   d_incl[N_MAX];
__device__ int   d_rs[N_MAX + 1];
__device__ int   d_cursor[N_MAX];
__device__ int   d_csr[E_MAX];
__device__ float d_dinv[N_MAX];
__device__ float d_sc[N_MAX];     // dinv/deg
__device__ int   d_bsum[256];
__device__ int   d_bpref[256];
// k-major W images: d_wimgT[l][k*128 + j] = W_l[j][k] (* imp[k] for l==0)
__device__ __align__(16) float d_wimgT[4][16384];

// ---------------- preprocessing: CSR-by-target + degree terms ----------------
__global__ void k_hist(const int* __restrict__ col, int e, int n) {
    int i = blockIdx.x * blockDim.x + threadIdx.x;
    if (i < e) {
        int c = col[i];
        if (c >= 0 && c < n) atomicAdd(&d_cnt[c], 1);
    }
}

__global__ void k_scan1(int n) {
    __shared__ int s[1024];
    int t = threadIdx.x;
    int i = blockIdx.x * 1024 + t;
    s[t] = (i < n) ? d_cnt[i] : 0;
    __syncthreads();
    for (int off = 1; off < 1024; off <<= 1) {
        int a = 0;
        if (t >= off) a = s[t - off];
        __syncthreads();
        s[t] += a;
        __syncthreads();
    }
    if (i < n) d_incl[i] = s[t];
    if (t == 1023) d_bsum[blockIdx.x] = s[1023];
}

__global__ void k_scan2(int nb) {   // single warp, shfl scan with carry
    int lane = threadIdx.x;
    int carry = 0;
    for (int base = 0; base < nb; base += 32) {
        int i = base + lane;
        int own = (i < nb) ? d_bsum[i] : 0;
        int v = own;
        #pragma unroll
        for (int o = 1; o < 32; o <<= 1) {
            int t = __shfl_up_sync(0xffffffffu, v, o);
            if (lane >= o) v += t;
        }
        if (i < nb) d_bpref[i] = carry + v - own;   // exclusive
        carry += __shfl_sync(0xffffffffu, v, 31);
    }
}

__global__ void k_scan3(int n) {
    int i = blockIdx.x * blockDim.x + threadIdx.x;
    if (i >= n) return;
    int gi = d_incl[i] + d_bpref[i >> 10];
    int c  = d_cnt[i];
    d_cnt[i] = 0;                        // re-zero for next graph replay
    int st = gi - c;
    d_rs[i] = st;
    d_cursor[i] = st;
    if (i == n - 1) d_rs[n] = gi;
    float deg = (float)(c + 1);          // degree incl. self-loop
    float di = rsqrtf(deg);
    d_dinv[i] = di;
    d_sc[i]   = di / deg;
}

__global__ void k_scatter(const int* __restrict__ ei, int e, int n) {
    int i = blockIdx.x * blockDim.x + threadIdx.x;
    if (i >= e) return;
    int c = ei[e + i];  // col (target)
    int r = ei[i];      // row (source)
    if (c < 0 || c >= n || r < 0 || r >= n) return;
    int pos = atomicAdd(&d_cursor[c], 1);
    d_csr[pos] = r;
}

// ---------------- W prep: k-major transpose (imp folded into layer 0) ----------------
__global__ void __launch_bounds__(256) k_prepw(
    const float* __restrict__ Wa, const float* __restrict__ Wb,
    const float* __restrict__ Wc, const float* __restrict__ Wd,
    const float* __restrict__ imp)
{
    int l = blockIdx.x;
    const float* W = (l == 0) ? Wa : (l == 1) ? Wb : (l == 2) ? Wc : Wd;
    for (int idx = threadIdx.x; idx < 16384; idx += 256) {
        int k = idx >> 7, j = idx & 127;
        float v = W[j * 128 + k];
        if (l == 0) v *= imp[k];
        d_wimgT[l][idx] = v;
    }
}

// ================= shared GEMM machinery =================
#define OFF_AS   65536
#define ASTAGE4  1024
#define GEMM_SMEM (65536 + 32768)           // 98304 B
#define HB_PITCH 133
#define OFF_WS2  68096
#define OFF_EXM  88576
#define OFF_EXS  89600

#define SCATTER_A(dstp) do { \
    int kb = lh * 16; \
    (dstp)[(kb + 0) * 128 + lr] = nxt0.x;  (dstp)[(kb + 1) * 128 + lr] = nxt0.y; \
    (dstp)[(kb + 2) * 128 + lr] = nxt0.z;  (dstp)[(kb + 3) * 128 + lr] = nxt0.w; \
    (dstp)[(kb + 4) * 128 + lr] = nxt1.x;  (dstp)[(kb + 5) * 128 + lr] = nxt1.y; \
    (dstp)[(kb + 6) * 128 + lr] = nxt1.z;  (dstp)[(kb + 7) * 128 + lr] = nxt1.w; \
    (dstp)[(kb + 8) * 128 + lr] = nxt2.x;  (dstp)[(kb + 9) * 128 + lr] = nxt2.y; \
    (dstp)[(kb +10) * 128 + lr] = nxt2.z;  (dstp)[(kb +11) * 128 + lr] = nxt2.w; \
    (dstp)[(kb +12) * 128 + lr] = nxt3.x;  (dstp)[(kb +13) * 128 + lr] = nxt3.y; \
    (dstp)[(kb +14) * 128 + lr] = nxt3.z;  (dstp)[(kb +15) * 128 + lr] = nxt3.w; \
} while (0)

#define LOAD_A_CHUNK(kc_) do { \
    nxt0 = nxt1 = nxt2 = nxt3 = make_float4(0.f, 0.f, 0.f, 0.f); \
    if (lgr < n) { \
        size_t b = (size_t)lgr * 32 + (kc_) * 8 + lh * 4; \
        nxt0 = S4[b + 0]; nxt1 = S4[b + 1]; nxt2 = S4[b + 2]; nxt3 = S4[b + 3]; \
    } \
} while (0)

#define FILL_BS() do { \
    const float4* wT4 = (const float4*)wT; \
    _Pragma("unroll") \
    for (int it = 0; it < 16; ++it) { \
        int idx = tid + it * 256; \
        int k = idx >> 5, j4 = idx & 31; \
        Bs4[k * 32 + (j4 ^ (k & 31))] = wT4[idx]; \
    } \
} while (0)

#define COMPUTE_CHUNK(kc_) do { \
    const float4* A4s = (const float4*)(Asf + ((kc_) & 1) * (ASTAGE4 * 4)); \
    int kbase = (kc_) * 32; \
    _Pragma("unroll 8") \
    for (int kl = 0; kl < 32; ++kl) { \
        float4 a0 = A4s[kl * 32 + ty]; \
        float4 a1 = A4s[kl * 32 + ty + 16]; \
        float4 b0 = Bs4[(kbase + kl) * 32 + (tx ^ kl)]; \
        float4 b1 = Bs4[(kbase + kl) * 32 + ((tx + 16) ^ kl)]; \
        float av[8] = {a0.x, a0.y, a0.z, a0.w, a1.x, a1.y, a1.z, a1.w}; \
        float bv[8] = {b0.x, b0.y, b0.z, b0.w, b1.x, b1.y, b1.z, b1.w}; \
        _Pragma("unroll") \
        for (int ii = 0; ii < 8; ii++) \
            _Pragma("unroll") \
            for (int jj = 0; jj < 8; jj++) \
                acc[ii][jj] += av[ii] * bv[jj]; \
    } \
} while (0)

// ---------------- persistent GEMM (layers 1-3): g = A @ W^T + bias -> bufB ----------------
__global__ void __launch_bounds__(256, 2) k_gemmp(
    const float* __restrict__ Aext,       // nullptr -> d_bufA
    const float* __restrict__ bias,
    int wsel, int n, int ntiles)
{
    extern __shared__ __align__(16) char sm[];
    float4* Bs4 = (float4*)sm;
    float*  Asf = (float*)(sm + OFF_AS);
    int tid = threadIdx.x;
    int tx = tid & 15, ty = tid >> 4;
    const float* A = Aext ? Aext : d_bufA;
    const float4* S4 = (const float4*)A;
    const float* wT = d_wimgT[wsel];
    int lr = tid >> 1, lh = tid & 1;

    FILL_BS();

    float4 nxt0, nxt1, nxt2, nxt3;
    for (int t = blockIdx.x; t < ntiles; t += gridDim.x) {
        int row0 = t * 128;
        int lgr = row0 + lr;

        LOAD_A_CHUNK(0);
        SCATTER_A(Asf);
        __syncthreads();

        float acc[8][8];
        #pragma unroll
        for (int i = 0; i < 8; i++)
            #pragma unroll
            for (int j = 0; j < 8; j++) acc[i][j] = 0.f;

        #pragma unroll
        for (int kc = 0; kc < 4; ++kc) {
            if (kc < 3) LOAD_A_CHUNK(kc + 1);
            COMPUTE_CHUNK(kc);
            if (kc < 3) {
                float* dst = Asf + ((kc + 1) & 1) * (ASTAGE4 * 4);
                SCATTER_A(dst);
                __syncthreads();
            }
        }

        #pragma unroll
        for (int ii = 0; ii < 8; ii++) {
            int gr = row0 + ty * 4 + (ii & 3) + (ii >> 2) * 64;
            if (gr >= n) continue;
            #pragma unroll
            for (int g = 0; g < 2; ++g) {
                int c0 = tx * 4 + g * 64;
                float4 o;
                o.x = acc[ii][g * 4 + 0] + bias[c0 + 0];
                o.y = acc[ii][g * 4 + 1] + bias[c0 + 1];
                o.z = acc[ii][g * 4 + 2] + bias[c0 + 2];
                o.w = acc[ii][g * 4 + 3] + bias[c0 + 3];
                *(float4*)(d_bufB + (size_t)gr * 128 + c0) = o;
            }
        }
    }
}

// ---------------- last layer: lin1 + relu, fused lin2 + log_softmax ----------------
__global__ void __launch_bounds__(256, 2) k_gemml(
    const float* __restrict__ bias,       // bli1
    int wsel,
    const float* __restrict__ Wl2,        // [40][128]
    const float* __restrict__ bl2,        // [40]
    float* __restrict__ out,              // [n][40]
    int n)
{
    extern __shared__ __align__(16) char sm[];
    float4* Bs4 = (float4*)sm;
    float*  Asf = (float*)(sm + OFF_AS);
    int tid = threadIdx.x;
    int tx = tid & 15, ty = tid >> 4;
    int row0 = blockIdx.x * 128;
    const float4* S4 = (const float4*)d_bufA;
    const float* wT = d_wimgT[wsel];
    int lr = tid >> 1, lh = tid & 1;
    int lgr = row0 + lr;

    float4 nxt0, nxt1, nxt2, nxt3;
    LOAD_A_CHUNK(0);
    FILL_BS();
    SCATTER_A(Asf);
    __syncthreads();

    float acc[8][8];
    #pragma unroll
    for (int i = 0; i < 8; i++)
        #pragma unroll
        for (int j = 0; j < 8; j++) acc[i][j] = 0.f;

    #pragma unroll
    for (int kc = 0; kc < 4; ++kc) {
        if (kc < 3) LOAD_A_CHUNK(kc + 1);
        COMPUTE_CHUNK(kc);
        if (kc < 3) {
            float* dst = Asf + ((kc + 1) & 1) * (ASTAGE4 * 4);
            SCATTER_A(dst);
            __syncthreads();
        }
    }

    // ---- fused lin2 + log_softmax (h = relu(acc + bias)) ----
    __syncthreads();
    float* hb  = (float*)sm;                // [128][HB_PITCH]
    float* Ws2 = (float*)(sm + OFF_WS2);    // Ws2[k*40 + c] = Wl2[c*128 + k]
    float* exm = (float*)(sm + OFF_EXM);
    float* exs = (float*)(sm + OFF_EXS);

    #pragma unroll
    for (int ii = 0; ii < 8; ii++) {
        int r = ty * 4 + (ii & 3) + (ii >> 2) * 64;
        #pragma unroll
        for (int g = 0; g < 2; ++g) {
            int c0 = tx * 4 + g * 64;
            hb[r * HB_PITCH + c0 + 0] = fmaxf(acc[ii][g * 4 + 0] + bias[c0 + 0], 0.f);
            hb[r * HB_PITCH + c0 + 1] = fmaxf(acc[ii][g * 4 + 1] + bias[c0 + 1], 0.f);
            hb[r * HB_PITCH + c0 + 2] = fmaxf(acc[ii][g * 4 + 2] + bias[c0 + 2], 0.f);
            hb[r * HB_PITCH + c0 + 3] = fmaxf(acc[ii][g * 4 + 3] + bias[c0 + 3], 0.f);
        }
    }
    for (int idx = tid; idx < 5120; idx += 256) {
        int c = idx >> 7, k = idx & 127;
        Ws2[k * 40 + c] = Wl2[idx];
    }
    __syncthreads();

    int row = tid & 127;
    int half = tid >> 7;
    int c0 = half * 20;

    float acc2[20];
    #pragma unroll
    for (int c = 0; c < 20; ++c) acc2[c] = bl2[c0 + c];

    const float* hr = hb + row * HB_PITCH;
    #pragma unroll 4
    for (int k = 0; k < 128; ++k) {
        float a = hr[k];
        const float2* w2 = (const float2*)(Ws2 + k * 40 + c0);
        #pragma unroll
        for (int q = 0; q < 10; ++q) {
            float2 w = w2[q];
            acc2[2 * q]     += a * w.x;
            acc2[2 * q + 1] += a * w.y;
        }
    }

    float m = acc2[0];
    #pragma unroll
    for (int c = 1; c < 20; ++c) m = fmaxf(m, acc2[c]);
    exm[half * 128 + row] = m;
    __syncthreads();
    m = fmaxf(exm[row], exm[128 + row]);

    float s = 0.f;
    #pragma unroll
    for (int c = 0; c < 20; ++c) s += __expf(acc2[c] - m);
    exs[half * 128 + row] = s;
    __syncthreads();
    s = exs[row] + exs[128 + row];
    float ls = m + __logf(s);

    int grow = row0 + row;
    if (grow < n) {
        float4* o4 = (float4*)(out + (size_t)grow * 40 + c0);
        #pragma unroll
        for (int q = 0; q < 5; ++q) {
            float4 o;
            o.x = acc2[q * 4 + 0] - ls;
            o.y = acc2[q * 4 + 1] - ls;
            o.z = acc2[q * 4 + 2] - ls;
            o.w = acc2[q * 4 + 3] - ls;
            o4[q] = o;
        }
    }
}

// ---------------- aggregation (dinv-weighted gather) ----------------
// bufA[c] = relu(sc[c]*(dinv[c]*g[c] + sum dinv[src]*g[src]) + bc)
__global__ void k_agg(const float* __restrict__ bc, int n)
{
    int w = (blockIdx.x * blockDim.x + threadIdx.x) >> 5;
    int lane = threadIdx.x & 31;
    if (w >= n) return;
    const float4* g = (const float4*)d_bufB;
    float dw = d_dinv[w];
    float4 v0 = g[w * 32 + lane];
    float4 s;
    s.x = dw * v0.x; s.y = dw * v0.y; s.z = dw * v0.z; s.w = dw * v0.w;
    int beg = d_rs[w], end = d_rs[w + 1];
    for (int e = beg; e < end; ++e) {
        int src = d_csr[e];
        float dv = d_dinv[src];
        float4 v = g[src * 32 + lane];
        s.x = fmaf(dv, v.x, s.x);
        s.y = fmaf(dv, v.y, s.y);
        s.z = fmaf(dv, v.z, s.z);
        s.w = fmaf(dv, v.w, s.w);
    }
    float kf = d_sc[w];
    float bx = bc[lane * 4 + 0], by = bc[lane * 4 + 1];
    float bz = bc[lane * 4 + 2], bw = bc[lane * 4 + 3];
    float4 o;
    o.x = fmaxf(kf * s.x + bx, 0.f);
    o.y = fmaxf(kf * s.y + by, 0.f);
    o.z = fmaxf(kf * s.z + bz, 0.f);
    o.w = fmaxf(kf * s.w + bw, 0.f);
    ((float4*)d_bufA)[w * 32 + lane] = o;
}

// ---------------- launch ----------------
extern "C" void kernel_launch(void* const* d_in, const int* in_sizes, int n_in,
                              void* d_out, int out_size)
{
    const float* x    = (const float*)d_in[0];
    const int*   ei   = (const int*)d_in[1];     // int32 (JAX x64 disabled)
    const float* imp  = (const float*)d_in[2];
    const float* W1   = (const float*)d_in[3];
    const float* bl1  = (const float*)d_in[4];
    const float* bc1  = (const float*)d_in[5];
    const float* W2   = (const float*)d_in[6];
    const float* bl2  = (const float*)d_in[7];
    const float* bc2  = (const float*)d_in[8];
    const float* W3   = (const float*)d_in[9];
    const float* bl3  = (const float*)d_in[10];
    const float* bc3  = (const float*)d_in[11];
    const float* Wl1  = (const float*)d_in[12];
    const float* bli1 = (const float*)d_in[13];
    const float* Wl2  = (const float*)d_in[14];
    const float* bli2 = (const float*)d_in[15];
    int n = in_sizes[0] / HF;
    int e = in_sizes[1] / 2;
    float* out = (float*)d_out;

    cudaFuncSetAttribute(k_gemmp, cudaFuncAttributeMaxDynamicSharedMemorySize, GEMM_SMEM);
    cudaFuncSetAttribute(k_gemml, cudaFuncAttributeMaxDynamicSharedMemorySize, GEMM_SMEM);

    // one-time stream/event handles (created on the uncaptured correctness call;
    // same work is enqueued on every call — deterministic)
    static cudaStream_t s2 = nullptr;
    static cudaEvent_t evFork = nullptr, evJoin = nullptr;
    if (!s2) {
        cudaStreamCreateWithFlags(&s2, cudaStreamNonBlocking);
        cudaEventCreateWithFlags(&evFork, cudaEventDisableTiming);
        cudaEventCreateWithFlags(&evJoin, cudaEventDisableTiming);
    }

    int ntiles = (n + 127) / 128;
    int pgrid = ntiles < 296 ? ntiles : 296;
    int ablocks = (n + 7) / 8;
    int nb = (n + 1023) / 1024;

    // fork: preprocessing chain on s2, concurrent with prepw + conv1 GEMM
    cudaEventRecord(evFork, 0);
    cudaStreamWaitEvent(s2, evFork, 0);

    k_hist   <<<(e + 255) / 256, 256, 0, s2>>>(ei + e, e, n);
    k_scan1  <<<nb, 1024, 0, s2>>>(n);
    k_scan2  <<<1, 32, 0, s2>>>(nb);
    k_scan3  <<<(n + 255) / 256, 256, 0, s2>>>(n);
    k_scatter<<<(e + 255) / 256, 256, 0, s2>>>(ei, e, n);
    cudaEventRecord(evJoin, s2);

    // main stream: W images + conv1 GEMM (independent of preproc now)
    k_prepw<<<4, 256>>>(W1, W2, W3, Wl1, imp);
    k_gemmp<<<pgrid, 256, GEMM_SMEM>>>(x, bl1, 0, n, ntiles);

    // join, then the serial chain
    cudaStreamWaitEvent(0, evJoin, 0);
    k_agg  <<<ablocks, 256>>>(bc1, n);
    k_gemmp<<<pgrid, 256, GEMM_SMEM>>>(nullptr, bl2, 1, n, ntiles);
    k_agg  <<<ablocks, 256>>>(bc2, n);
    k_gemmp<<<pgrid, 256, GEMM_SMEM>>>(nullptr, bl3, 2, n, ntiles);
    k_agg  <<<ablocks, 256>>>(bc3, n);
    k_gemml<<<ntiles, 256, GEMM_SMEM>>>(bli1, 3, Wl2, bli2, out, n);
}

// round 15
// speedup vs baseline: 1.0599x; 1.0599x over previous
#include <cuda_runtime.h>
#include <cstdint>

#define N_MAX 100000
#define E_MAX 600000
#define HF 128

// ---------------- scratch (static __device__ — no allocation) ----------------
__device__ __align__(16) float d_bufA[N_MAX * HF];
__device__ __align__(16) float d_bufB[N_MAX * HF];
__device__ int   d_cnt[N_MAX];
__device__ int   d_incl[N_MAX];
__device__ int   d_rs[N_MAX + 1];
__device__ int   d_cursor[N_MAX];
__device__ int   d_csr[E_MAX];
__device__ float d_dinv[N_MAX];
__device__ float d_sc[N_MAX];     // dinv/deg
__device__ int   d_bsum[256];
__device__ int   d_bpref[256];
// k-major W images: d_wimgT[l][k*128 + j] = W_l[j][k] (* imp[k] for l==0)
__device__ __align__(16) float d_wimgT[4][16384];

// ---------------- preprocessing: CSR-by-target + degree terms ----------------
__global__ void k_hist(const int* __restrict__ col, int e, int n) {
    int i = blockIdx.x * blockDim.x + threadIdx.x;
    if (i < e) {
        int c = col[i];
        if (c >= 0 && c < n) atomicAdd(&d_cnt[c], 1);
    }
}

__global__ void k_scan1(int n) {
    __shared__ int s[1024];
    int t = threadIdx.x;
    int i = blockIdx.x * 1024 + t;
    s[t] = (i < n) ? d_cnt[i] : 0;
    __syncthreads();
    for (int off = 1; off < 1024; off <<= 1) {
        int a = 0;
        if (t >= off) a = s[t - off];
        __syncthreads();
        s[t] += a;
        __syncthreads();
    }
    if (i < n) d_incl[i] = s[t];
    if (t == 1023) d_bsum[blockIdx.x] = s[1023];
}

__global__ void k_scan2(int nb) {   // single warp, shfl scan with carry
    int lane = threadIdx.x;
    int carry = 0;
    for (int base = 0; base < nb; base += 32) {
        int i = base + lane;
        int own = (i < nb) ? d_bsum[i] : 0;
        int v = own;
        #pragma unroll
        for (int o = 1; o < 32; o <<= 1) {
            int t = __shfl_up_sync(0xffffffffu, v, o);
            if (lane >= o) v += t;
        }
        if (i < nb) d_bpref[i] = carry + v - own;   // exclusive
        carry += __shfl_sync(0xffffffffu, v, 31);
    }
}

__global__ void k_scan3(int n) {
    int i = blockIdx.x * blockDim.x + threadIdx.x;
    if (i >= n) return;
    int gi = d_incl[i] + d_bpref[i >> 10];
    int c  = d_cnt[i];
    d_cnt[i] = 0;                        // re-zero for next graph replay
    int st = gi - c;
    d_rs[i] = st;
    d_cursor[i] = st;
    if (i == n - 1) d_rs[n] = gi;
    float deg = (float)(c + 1);          // degree incl. self-loop
    float di = rsqrtf(deg);
    d_dinv[i] = di;
    d_sc[i]   = di / deg;
}

__global__ void k_scatter(const int* __restrict__ ei, int e, int n) {
    int i = blockIdx.x * blockDim.x + threadIdx.x;
    if (i >= e) return;
    int c = ei[e + i];  // col (target)
    int r = ei[i];      // row (source)
    if (c < 0 || c >= n || r < 0 || r >= n) return;
    int pos = atomicAdd(&d_cursor[c], 1);
    d_csr[pos] = r;
}

// ---------------- W prep: k-major transpose (imp folded into layer 0) ----------------
__global__ void __launch_bounds__(256) k_prepw(
    const float* __restrict__ Wa, const float* __restrict__ Wb,
    const float* __restrict__ Wc, const float* __restrict__ Wd,
    const float* __restrict__ imp)
{
    int l = blockIdx.x;
    const float* W = (l == 0) ? Wa : (l == 1) ? Wb : (l == 2) ? Wc : Wd;
    for (int idx = threadIdx.x; idx < 16384; idx += 256) {
        int k = idx >> 7, j = idx & 127;
        float v = W[j * 128 + k];
        if (l == 0) v *= imp[k];
        d_wimgT[l][idx] = v;
    }
}

// ================= shared GEMM machinery =================
#define OFF_AS   65536
#define ASTAGE4  1024
#define GEMM_SMEM (65536 + 32768)           // 98304 B
#define HB_PITCH 133
#define OFF_WS2  68096
#define OFF_EXM  88576
#define OFF_EXS  89600

#define SCATTER_A(dstp) do { \
    int kb = lh * 16; \
    (dstp)[(kb + 0) * 128 + lr] = nxt0.x;  (dstp)[(kb + 1) * 128 + lr] = nxt0.y; \
    (dstp)[(kb + 2) * 128 + lr] = nxt0.z;  (dstp)[(kb + 3) * 128 + lr] = nxt0.w; \
    (dstp)[(kb + 4) * 128 + lr] = nxt1.x;  (dstp)[(kb + 5) * 128 + lr] = nxt1.y; \
    (dstp)[(kb + 6) * 128 + lr] = nxt1.z;  (dstp)[(kb + 7) * 128 + lr] = nxt1.w; \
    (dstp)[(kb + 8) * 128 + lr] = nxt2.x;  (dstp)[(kb + 9) * 128 + lr] = nxt2.y; \
    (dstp)[(kb +10) * 128 + lr] = nxt2.z;  (dstp)[(kb +11) * 128 + lr] = nxt2.w; \
    (dstp)[(kb +12) * 128 + lr] = nxt3.x;  (dstp)[(kb +13) * 128 + lr] = nxt3.y; \
    (dstp)[(kb +14) * 128 + lr] = nxt3.z;  (dstp)[(kb +15) * 128 + lr] = nxt3.w; \
} while (0)

#define LOAD_A_CHUNK(kc_) do { \
    nxt0 = nxt1 = nxt2 = nxt3 = make_float4(0.f, 0.f, 0.f, 0.f); \
    if (lgr < n) { \
        size_t b = (size_t)lgr * 32 + (kc_) * 8 + lh * 4; \
        nxt0 = S4[b + 0]; nxt1 = S4[b + 1]; nxt2 = S4[b + 2]; nxt3 = S4[b + 3]; \
    } \
} while (0)

#define FILL_BS() do { \
    const float4* wT4 = (const float4*)wT; \
    _Pragma("unroll") \
    for (int it = 0; it < 16; ++it) { \
        int idx = tid + it * 256; \
        int k = idx >> 5, j4 = idx & 31; \
        Bs4[k * 32 + (j4 ^ (k & 31))] = wT4[idx]; \
    } \
} while (0)

#define COMPUTE_CHUNK(kc_) do { \
    const float4* A4s = (const float4*)(Asf + ((kc_) & 1) * (ASTAGE4 * 4)); \
    int kbase = (kc_) * 32; \
    _Pragma("unroll 8") \
    for (int kl = 0; kl < 32; ++kl) { \
        float4 a0 = A4s[kl * 32 + ty]; \
        float4 a1 = A4s[kl * 32 + ty + 16]; \
        float4 b0 = Bs4[(kbase + kl) * 32 + (tx ^ kl)]; \
        float4 b1 = Bs4[(kbase + kl) * 32 + ((tx + 16) ^ kl)]; \
        float av[8] = {a0.x, a0.y, a0.z, a0.w, a1.x, a1.y, a1.z, a1.w}; \
        float bv[8] = {b0.x, b0.y, b0.z, b0.w, b1.x, b1.y, b1.z, b1.w}; \
        _Pragma("unroll") \
        for (int ii = 0; ii < 8; ii++) \
            _Pragma("unroll") \
            for (int jj = 0; jj < 8; jj++) \
                acc[ii][jj] += av[ii] * bv[jj]; \
    } \
} while (0)

// ---------------- persistent GEMM (layers 1-3): g = rowscale*(A @ W^T + bias) -> bufB ----
__global__ void __launch_bounds__(256, 2) k_gemmp(
    const float* __restrict__ Aext,       // nullptr -> d_bufA
    const float* __restrict__ bias,
    int wsel, int use_dinv,
    int n, int ntiles)
{
    extern __shared__ __align__(16) char sm[];
    float4* Bs4 = (float4*)sm;
    float*  Asf = (float*)(sm + OFF_AS);
    int tid = threadIdx.x;
    int tx = tid & 15, ty = tid >> 4;
    const float* A = Aext ? Aext : d_bufA;
    const float4* S4 = (const float4*)A;
    const float* wT = d_wimgT[wsel];
    int lr = tid >> 1, lh = tid & 1;

    FILL_BS();

    float4 nxt0, nxt1, nxt2, nxt3;
    for (int t = blockIdx.x; t < ntiles; t += gridDim.x) {
        int row0 = t * 128;
        int lgr = row0 + lr;

        LOAD_A_CHUNK(0);
        SCATTER_A(Asf);
        __syncthreads();

        float acc[8][8];
        #pragma unroll
        for (int i = 0; i < 8; i++)
            #pragma unroll
            for (int j = 0; j < 8; j++) acc[i][j] = 0.f;

        #pragma unroll
        for (int kc = 0; kc < 4; ++kc) {
            if (kc < 3) LOAD_A_CHUNK(kc + 1);
            COMPUTE_CHUNK(kc);
            if (kc < 3) {
                float* dst = Asf + ((kc + 1) & 1) * (ASTAGE4 * 4);
                SCATTER_A(dst);
                __syncthreads();
            }
        }

        #pragma unroll
        for (int ii = 0; ii < 8; ii++) {
            int gr = row0 + ty * 4 + (ii & 3) + (ii >> 2) * 64;
            if (gr >= n) continue;
            float rs = use_dinv ? d_dinv[gr] : 1.f;
            #pragma unroll
            for (int g = 0; g < 2; ++g) {
                int c0 = tx * 4 + g * 64;
                float4 o;
                o.x = (acc[ii][g * 4 + 0] + bias[c0 + 0]) * rs;
                o.y = (acc[ii][g * 4 + 1] + bias[c0 + 1]) * rs;
                o.z = (acc[ii][g * 4 + 2] + bias[c0 + 2]) * rs;
                o.w = (acc[ii][g * 4 + 3] + bias[c0 + 3]) * rs;
                *(float4*)(d_bufB + (size_t)gr * 128 + c0) = o;
            }
        }
    }
}

// ---------------- last layer: lin1 + relu, fused lin2 + log_softmax ----------------
__global__ void __launch_bounds__(256, 2) k_gemml(
    const float* __restrict__ bias,       // bli1
    int wsel,
    const float* __restrict__ Wl2,        // [40][128]
    const float* __restrict__ bl2,        // [40]
    float* __restrict__ out,              // [n][40]
    int n)
{
    extern __shared__ __align__(16) char sm[];
    float4* Bs4 = (float4*)sm;
    float*  Asf = (float*)(sm + OFF_AS);
    int tid = threadIdx.x;
    int tx = tid & 15, ty = tid >> 4;
    int row0 = blockIdx.x * 128;
    const float4* S4 = (const float4*)d_bufA;
    const float* wT = d_wimgT[wsel];
    int lr = tid >> 1, lh = tid & 1;
    int lgr = row0 + lr;

    float4 nxt0, nxt1, nxt2, nxt3;
    LOAD_A_CHUNK(0);
    FILL_BS();
    SCATTER_A(Asf);
    __syncthreads();

    float acc[8][8];
    #pragma unroll
    for (int i = 0; i < 8; i++)
        #pragma unroll
        for (int j = 0; j < 8; j++) acc[i][j] = 0.f;

    #pragma unroll
    for (int kc = 0; kc < 4; ++kc) {
        if (kc < 3) LOAD_A_CHUNK(kc + 1);
        COMPUTE_CHUNK(kc);
        if (kc < 3) {
            float* dst = Asf + ((kc + 1) & 1) * (ASTAGE4 * 4);
            SCATTER_A(dst);
            __syncthreads();
        }
    }

    // ---- fused lin2 + log_softmax (h = relu(acc + bias)) ----
    __syncthreads();
    float* hb  = (float*)sm;                // [128][HB_PITCH]
    float* Ws2 = (float*)(sm + OFF_WS2);    // Ws2[k*40 + c] = Wl2[c*128 + k]
    float* exm = (float*)(sm + OFF_EXM);
    float* exs = (float*)(sm + OFF_EXS);

    #pragma unroll
    for (int ii = 0; ii < 8; ii++) {
        int r = ty * 4 + (ii & 3) + (ii >> 2) * 64;
        #pragma unroll
        for (int g = 0; g < 2; ++g) {
            int c0 = tx * 4 + g * 64;
            hb[r * HB_PITCH + c0 + 0] = fmaxf(acc[ii][g * 4 + 0] + bias[c0 + 0], 0.f);
            hb[r * HB_PITCH + c0 + 1] = fmaxf(acc[ii][g * 4 + 1] + bias[c0 + 1], 0.f);
            hb[r * HB_PITCH + c0 + 2] = fmaxf(acc[ii][g * 4 + 2] + bias[c0 + 2], 0.f);
            hb[r * HB_PITCH + c0 + 3] = fmaxf(acc[ii][g * 4 + 3] + bias[c0 + 3], 0.f);
        }
    }
    for (int idx = tid; idx < 5120; idx += 256) {
        int c = idx >> 7, k = idx & 127;
        Ws2[k * 40 + c] = Wl2[idx];
    }
    __syncthreads();

    int row = tid & 127;
    int half = tid >> 7;
    int c0 = half * 20;

    float acc2[20];
    #pragma unroll
    for (int c = 0; c < 20; ++c) acc2[c] = bl2[c0 + c];

    const float* hr = hb + row * HB_PITCH;
    #pragma unroll 4
    for (int k = 0; k < 128; ++k) {
        float a = hr[k];
        const float2* w2 = (const float2*)(Ws2 + k * 40 + c0);
        #pragma unroll
        for (int q = 0; q < 10; ++q) {
            float2 w = w2[q];
            acc2[2 * q]     += a * w.x;
            acc2[2 * q + 1] += a * w.y;
        }
    }

    float m = acc2[0];
    #pragma unroll
    for (int c = 1; c < 20; ++c) m = fmaxf(m, acc2[c]);
    exm[half * 128 + row] = m;
    __syncthreads();
    m = fmaxf(exm[row], exm[128 + row]);

    float s = 0.f;
    #pragma unroll
    for (int c = 0; c < 20; ++c) s += __expf(acc2[c] - m);
    exs[half * 128 + row] = s;
    __syncthreads();
    s = exs[row] + exs[128 + row];
    float ls = m + __logf(s);

    int grow = row0 + row;
    if (grow < n) {
        float4* o4 = (float4*)(out + (size_t)grow * 40 + c0);
        #pragma unroll
        for (int q = 0; q < 5; ++q) {
            float4 o;
            o.x = acc2[q * 4 + 0] - ls;
            o.y = acc2[q * 4 + 1] - ls;
            o.z = acc2[q * 4 + 2] - ls;
            o.w = acc2[q * 4 + 3] - ls;
            o4[q] = o;
        }
    }
}

// ---------------- aggregation ----------------
// weighted=0: bufA[c] = relu(sc[c]*(g[c] + sum g[src]) + bc)          [g pre-scaled]
// weighted=1: bufA[c] = relu(sc[c]*(dinv[c]*g[c] + sum dinv[s]*g[s]) + bc)
__global__ void k_agg(const float* __restrict__ bc, int n, int weighted)
{
    int w = (blockIdx.x * blockDim.x + threadIdx.x) >> 5;
    int lane = threadIdx.x & 31;
    if (w >= n) return;
    const float4* g = (const float4*)d_bufB;
    float4 s;
    int beg = d_rs[w], end = d_rs[w + 1];
    if (weighted) {
        float dw = d_dinv[w];
        float4 v0 = g[w * 32 + lane];
        s.x = dw * v0.x; s.y = dw * v0.y; s.z = dw * v0.z; s.w = dw * v0.w;
        for (int e = beg; e < end; ++e) {
            int src = d_csr[e];
            float dv = d_dinv[src];
            float4 v = g[src * 32 + lane];
            s.x = fmaf(dv, v.x, s.x);
            s.y = fmaf(dv, v.y, s.y);
            s.z = fmaf(dv, v.z, s.z);
            s.w = fmaf(dv, v.w, s.w);
        }
    } else {
        s = g[w * 32 + lane];
        for (int e = beg; e < end; ++e) {
            int src = d_csr[e];
            float4 v = g[src * 32 + lane];
            s.x += v.x; s.y += v.y; s.z += v.z; s.w += v.w;
        }
    }
    float kf = d_sc[w];
    float bx = bc[lane * 4 + 0], by = bc[lane * 4 + 1];
    float bz = bc[lane * 4 + 2], bw = bc[lane * 4 + 3];
    float4 o;
    o.x = fmaxf(kf * s.x + bx, 0.f);
    o.y = fmaxf(kf * s.y + by, 0.f);
    o.z = fmaxf(kf * s.z + bz, 0.f);
    o.w = fmaxf(kf * s.w + bw, 0.f);
    ((float4*)d_bufA)[w * 32 + lane] = o;
}

// ---------------- launch ----------------
extern "C" void kernel_launch(void* const* d_in, const int* in_sizes, int n_in,
                              void* d_out, int out_size)
{
    const float* x    = (const float*)d_in[0];
    const int*   ei   = (const int*)d_in[1];     // int32 (JAX x64 disabled)
    const float* imp  = (const float*)d_in[2];
    const float* W1   = (const float*)d_in[3];
    const float* bl1  = (const float*)d_in[4];
    const float* bc1  = (const float*)d_in[5];
    const float* W2   = (const float*)d_in[6];
    const float* bl2  = (const float*)d_in[7];
    const float* bc2  = (const float*)d_in[8];
    const float* W3   = (const float*)d_in[9];
    const float* bl3  = (const float*)d_in[10];
    const float* bc3  = (const float*)d_in[11];
    const float* Wl1  = (const float*)d_in[12];
    const float* bli1 = (const float*)d_in[13];
    const float* Wl2  = (const float*)d_in[14];
    const float* bli2 = (const float*)d_in[15];
    int n = in_sizes[0] / HF;
    int e = in_sizes[1] / 2;
    float* out = (float*)d_out;

    cudaFuncSetAttribute(k_gemmp, cudaFuncAttributeMaxDynamicSharedMemorySize, GEMM_SMEM);
    cudaFuncSetAttribute(k_gemml, cudaFuncAttributeMaxDynamicSharedMemorySize, GEMM_SMEM);

    static cudaStream_t s2 = nullptr;
    static cudaEvent_t evFork = nullptr, evJoin = nullptr;
    if (!s2) {
        cudaStreamCreateWithFlags(&s2, cudaStreamNonBlocking);
        cudaEventCreateWithFlags(&evFork, cudaEventDisableTiming);
        cudaEventCreateWithFlags(&evJoin, cudaEventDisableTiming);
    }

    int ntiles = (n + 127) / 128;
    int pgrid  = ntiles < 296 ? ntiles : 296;   // layers 2-3: full occupancy
    int pgrid1 = ntiles < 264 ? ntiles : 264;   // conv1: leave 16 SMs for preproc
    int ablocks = (n + 7) / 8;
    int nb = (n + 1023) / 1024;

    // fork: preprocessing chain on s2, truly concurrent with conv1 (free SMs)
    cudaEventRecord(evFork, 0);
    cudaStreamWaitEvent(s2, evFork, 0);

    k_hist   <<<(e + 255) / 256, 256, 0, s2>>>(ei + e, e, n);
    k_scan1  <<<nb, 1024, 0, s2>>>(n);
    k_scan2  <<<1, 32, 0, s2>>>(nb);
    k_scan3  <<<(n + 255) / 256, 256, 0, s2>>>(n);
    k_scatter<<<(e + 255) / 256, 256, 0, s2>>>(ei, e, n);
    cudaEventRecord(evJoin, s2);

    // main stream: W images + conv1 GEMM (no dinv dependency: weighted agg below)
    k_prepw<<<4, 256>>>(W1, W2, W3, Wl1, imp);
    k_gemmp<<<pgrid1, 256, GEMM_SMEM>>>(x, bl1, 0, 0, n, ntiles);

    cudaStreamWaitEvent(0, evJoin, 0);
    k_agg  <<<ablocks, 256>>>(bc1, n, 1);                        // dinv-weighted
    k_gemmp<<<pgrid, 256, GEMM_SMEM>>>(nullptr, bl2, 1, 1, n, ntiles);
    k_agg  <<<ablocks, 256>>>(bc2, n, 0);
    k_gemmp<<<pgrid, 256, GEMM_SMEM>>>(nullptr, bl3, 2, 1, n, ntiles);
    k_agg  <<<ablocks, 256>>>(bc3, n, 0);
    k_gemml<<<ntiles, 256, GEMM_SMEM>>>(bli1, 3, Wl2, bli2, out, n);
}